// round 8
// baseline (speedup 1.0000x reference)
#include <cuda_runtime.h>

#define TT 4
#define BB 32
#define CC 384
#define NP 196
#define HH 8
#define HD 48
#define LB (TT*BB)     // 128 (t,b) batches
#define KD 384
#define M1 1152        // stacked q,k,v output channels
#define NCOLS (LB*NP)  // 25088 flattened columns
#define NTILES (NCOLS/64)  // 392 exactly

typedef unsigned long long u64;

// ---------------- packed f32x2 helpers (Blackwell FFMA2) ----------------
__device__ __forceinline__ u64 pk2(float x) {
    u64 d; asm("mov.b64 %0, {%1, %2};" : "=l"(d) : "f"(x), "f"(x)); return d;
}
__device__ __forceinline__ u64 fma2(u64 a, u64 b, u64 c) {
    u64 d; asm("fma.rn.f32x2 %0, %1, %2, %3;" : "=l"(d) : "l"(a), "l"(b), "l"(c)); return d;
}
__device__ __forceinline__ u64 add2(u64 a, u64 b) {
    u64 d; asm("add.rn.f32x2 %0, %1, %2;" : "=l"(d) : "l"(a), "l"(b)); return d;
}

// ---------------- scratch (static device globals; no allocs) ----------------
__device__ float    g_wqkv[M1*KD];                 // folded scale*W for q,k,v stacked
__device__ float    g_bqkv[M1];
__device__ float    g_wp[CC*KD];                   // folded proj weight
__device__ float    g_bp[CC];
__device__ float    g_y1[(size_t)LB*M1*NP];        // pre-LIF qkv activations
__device__ unsigned g_s1[3*TT*BB*CC*8];            // packed spike bits
__device__ float    g_s2[(size_t)LB*CC*NP];        // attn-LIF spikes as 0/1 floats
__device__ float    g_y3[(size_t)LB*CC*NP];        // pre-LIF proj activations

// ---------------- weight folding ----------------
__global__ void prep_kernel(const float* __restrict__ wq, const float* __restrict__ sq, const float* __restrict__ bq,
                            const float* __restrict__ wk, const float* __restrict__ sk, const float* __restrict__ bk,
                            const float* __restrict__ wv, const float* __restrict__ sv, const float* __restrict__ bv,
                            const float* __restrict__ wp, const float* __restrict__ sp, const float* __restrict__ bp)
{
    int idx = blockIdx.x * blockDim.x + threadIdx.x;
    if (idx < M1*KD) {
        int co = idx / KD, c = idx - co*KD;
        int s  = co / CC,  cp = co - s*CC;
        const float* w  = (s==0) ? wq : (s==1 ? wk : wv);
        const float* sc = (s==0) ? sq : (s==1 ? sk : sv);
        g_wqkv[idx] = w[cp*KD + c] * sc[cp];
        if (c == 0) {
            const float* bi = (s==0) ? bq : (s==1 ? bk : bv);
            g_bqkv[co] = bi[cp];
        }
    } else {
        int j = idx - M1*KD;
        if (j < CC*KD) {
            int cp = j / KD, c = j - cp*KD;
            g_wp[j] = wp[j] * sp[cp];
            if (c == 0) g_bp[cp] = bp[cp];
        }
    }
}

// ---------------- FFMA2 batched GEMM over flattened (l,n) columns ----------------
// C[m, (l,n)] = sum_k A[m,k] * B[l][k,n] + bias[m]
// B memory layout: [l][KD][NP] (x or g_s2).  C layout: [l][M][NP].
// Flattened col cg = l*196 + n; tiles of 64 cols never need bounds checks
// (25088 % 64 == 0) and float4/float2 column groups never cross l (196 % 4 == 0).
// Block: 128 threads, tile 64M x 64N, micro 4M x 8N (4 packed pairs), K-tile 16.
__global__ void __launch_bounds__(128) gemm_kernel(const float* __restrict__ Bext, int stage)
{
    const float* __restrict__ A   = stage ? g_wp  : g_wqkv;
    const float* __restrict__ bia = stage ? g_bp  : g_bqkv;
    const float* __restrict__ Bb  = stage ? g_s2  : Bext;
    float*       __restrict__ Cb  = stage ? g_y3  : g_y1;
    const int M = stage ? CC : M1;

    const int m0 = blockIdx.y * 64;
    const int n0 = blockIdx.x * 64;

    __shared__ float As[16][68];   // [k][m] padded (stride 272B, 16B aligned)
    __shared__ float Bs[16][68];   // [k][n] padded

    const int tid = threadIdx.x;
    const int tx = tid & 7;        // N group (8 cols)
    const int ty = tid >> 3;       // M group (4 rows)

    // ---- A loader: row am, k-quads q0 and q0+2 ----
    const int am = tid >> 1;
    const int q0 = (tid & 1);
    const float* Aptr = A + (size_t)(m0 + am) * KD + q0*4;

    // ---- B loader: k-row bk, col-quads bq and bq+8 ----
    const int bk = tid >> 3;
    const int bq = tid & 7;
    int cg0 = n0 + bq*4;
    int cg1 = n0 + (bq+8)*4;
    int l0 = cg0 / NP, nn0 = cg0 - l0*NP;
    int l1 = cg1 / NP, nn1 = cg1 - l1*NP;
    const float* Bptr0 = Bb + (size_t)l0 * KD * NP + (size_t)bk * NP + nn0;
    const float* Bptr1 = Bb + (size_t)l1 * KD * NP + (size_t)bk * NP + nn1;

    u64 acc[4][4];
#pragma unroll
    for (int i = 0; i < 4; i++)
#pragma unroll
        for (int p = 0; p < 4; p++) acc[i][p] = 0ull;

    // prefetch k0 = 0
    float4 ar0 = *(const float4*)(Aptr);
    float4 ar1 = *(const float4*)(Aptr + 8);
    float4 br0 = *(const float4*)(Bptr0);
    float4 br1 = *(const float4*)(Bptr1);

    for (int k0 = 0; k0 < KD; k0 += 16) {
        // store staged regs to smem (A transposed to [k][m])
        As[q0*4+0][am] = ar0.x;  As[q0*4+1][am] = ar0.y;
        As[q0*4+2][am] = ar0.z;  As[q0*4+3][am] = ar0.w;
        As[q0*4+8][am] = ar1.x;  As[q0*4+9][am] = ar1.y;
        As[q0*4+10][am] = ar1.z; As[q0*4+11][am] = ar1.w;
        *(float4*)&Bs[bk][bq*4]      = br0;
        *(float4*)&Bs[bk][bq*4 + 32] = br1;
        __syncthreads();

        if (k0 + 16 < KD) {
            ar0 = *(const float4*)(Aptr + k0 + 16);
            ar1 = *(const float4*)(Aptr + k0 + 24);
            br0 = *(const float4*)(Bptr0 + (size_t)(k0 + 16) * NP);
            br1 = *(const float4*)(Bptr1 + (size_t)(k0 + 16) * NP);
        }

#pragma unroll
        for (int kk = 0; kk < 16; kk++) {
            float4 af = *(const float4*)&As[kk][ty*4];
            ulonglong2 bp0 = *(const ulonglong2*)&Bs[kk][tx*8];
            ulonglong2 bp1 = *(const ulonglong2*)&Bs[kk][tx*8 + 4];
            u64 a0 = pk2(af.x), a1 = pk2(af.y), a2 = pk2(af.z), a3 = pk2(af.w);
            acc[0][0] = fma2(a0, bp0.x, acc[0][0]);
            acc[0][1] = fma2(a0, bp0.y, acc[0][1]);
            acc[0][2] = fma2(a0, bp1.x, acc[0][2]);
            acc[0][3] = fma2(a0, bp1.y, acc[0][3]);
            acc[1][0] = fma2(a1, bp0.x, acc[1][0]);
            acc[1][1] = fma2(a1, bp0.y, acc[1][1]);
            acc[1][2] = fma2(a1, bp1.x, acc[1][2]);
            acc[1][3] = fma2(a1, bp1.y, acc[1][3]);
            acc[2][0] = fma2(a2, bp0.x, acc[2][0]);
            acc[2][1] = fma2(a2, bp0.y, acc[2][1]);
            acc[2][2] = fma2(a2, bp1.x, acc[2][2]);
            acc[2][3] = fma2(a2, bp1.y, acc[2][3]);
            acc[3][0] = fma2(a3, bp0.x, acc[3][0]);
            acc[3][1] = fma2(a3, bp0.y, acc[3][1]);
            acc[3][2] = fma2(a3, bp1.x, acc[3][2]);
            acc[3][3] = fma2(a3, bp1.y, acc[3][3]);
        }
        __syncthreads();
    }

    // ---- epilogue: bias + store as aligned 8B pairs ----
    size_t coff[4];
#pragma unroll
    for (int p = 0; p < 4; p++) {
        int cg = n0 + tx*8 + 2*p;          // even -> pair stays within one l
        int l = cg / NP;
        int nn = cg - l*NP;
        coff[p] = (size_t)l * M * NP + nn;
    }
#pragma unroll
    for (int i = 0; i < 4; i++) {
        int m = m0 + ty*4 + i;
        u64 bb = pk2(bia[m]);
#pragma unroll
        for (int p = 0; p < 4; p++) {
            u64 r = add2(acc[i][p], bb);
            *(u64*)(Cb + coff[p] + (size_t)m * NP) = r;
        }
    }
}

// ---------------- LIF over T for qkv + pack spikes to bits ----------------
__global__ void __launch_bounds__(224) lif1_kernel()
{
    const int r = blockIdx.x;                 // 0 .. 3*32*384-1
    const int s = r / (BB*CC);
    const int rem = r - s*BB*CC;
    const int b = rem / CC;
    const int c = rem - b*CC;

    const int n = threadIdx.x;
    const int w = n >> 5, lane = n & 31;
    const bool valid = (n < NP);

    const size_t tstride = (size_t)BB * M1 * NP;
    const float* ybase = g_y1 + ((size_t)b*M1 + s*CC + c) * NP + n;

    float v = 0.f;
#pragma unroll
    for (int t = 0; t < TT; t++) {
        float y = valid ? ybase[(size_t)t * tstride] : 0.f;
        v += (y - v) * 0.5f;
        int sp = valid && (v >= 1.f);
        unsigned m = __ballot_sync(0xffffffffu, sp);
        unsigned base = (((unsigned)(s*TT + t) * BB + b) * CC + c) * 8u;
        if (lane == 0) g_s1[base + w] = m;
        if (n == 0)    g_s1[base + 7] = 0u;     // pad word
        if (sp) v = 0.f;
    }
}

// ---------------- attention: out = Q (K^T V) * 0.125, fused attn-LIF(0.5) ----------------
__global__ void __launch_bounds__(224) attn_kernel()
{
    const int bh = blockIdx.x;
    const int b = bh >> 3;
    const int h = bh & 7;

    __shared__ unsigned qb[HD][8], kb[HD][8], vb[HD][8];
    __shared__ float KVf[HD][HD];

    const int tid = threadIdx.x;
    const int n = tid;
    const bool valid = (n < NP);
    const int wq_ = n >> 5, sh = n & 31;

    float vstate[HD];
#pragma unroll
    for (int j = 0; j < HD; j++) vstate[j] = 0.f;

    for (int t = 0; t < TT; t++) {
        for (int i = tid; i < 3*CC; i += 224) {
            int s = i / CC;
            int rr = i - s*CC;
            int dd = rr >> 3, w = rr & 7;
            unsigned val = g_s1[(((unsigned)(s*TT + t) * BB + b) * CC + h*HD + dd) * 8u + w];
            unsigned (*dst)[8] = (s == 0) ? qb : (s == 1 ? kb : vb);
            dst[dd][w] = val;
        }
        __syncthreads();

        for (int p = tid; p < HD*HD; p += 224) {
            int dd = p / HD, d2 = p - dd*HD;
            int cnt = 0;
#pragma unroll
            for (int w = 0; w < 7; w++) cnt += __popc(kb[dd][w] & vb[d2][w]);
            KVf[dd][d2] = (float)cnt;
        }
        __syncthreads();

        if (valid) {
            float acc[HD];
#pragma unroll
            for (int j = 0; j < HD; j++) acc[j] = 0.f;

            for (int dd = 0; dd < HD; dd++) {
                float bf = (float)((qb[dd][wq_] >> sh) & 1u);
#pragma unroll
                for (int j = 0; j < HD; j++) acc[j] += bf * KVf[dd][j];
            }

            float* s2 = g_s2 + (((size_t)t*BB + b) * CC + h*HD) * NP + n;
#pragma unroll
            for (int j = 0; j < HD; j++) {
                float y = acc[j] * 0.125f;
                float v = vstate[j];
                v += (y - v) * 0.5f;
                bool sp = (v >= 0.5f);
                s2[(size_t)j * NP] = sp ? 1.f : 0.f;
                vstate[j] = sp ? 0.f : v;
            }
        }
        __syncthreads();
    }
}

// ---------------- final LIF over T -> output spikes ----------------
__global__ void lif2_kernel(float* __restrict__ out)
{
    const int S = BB*CC*NP;
    int idx = blockIdx.x * blockDim.x + threadIdx.x;
    if (idx >= S) return;
    float v = 0.f;
#pragma unroll
    for (int t = 0; t < TT; t++) {
        float y = g_y3[(size_t)t * S + idx];
        v += (y - v) * 0.5f;
        if (v >= 1.f) { out[(size_t)t * S + idx] = 1.f; v = 0.f; }
        else          { out[(size_t)t * S + idx] = 0.f; }
    }
}

// ---------------- launch ----------------
extern "C" void kernel_launch(void* const* d_in, const int* in_sizes, int n_in,
                              void* d_out, int out_size)
{
    const float* x  = (const float*)d_in[0];
    const float* wq = (const float*)d_in[1];
    const float* sq = (const float*)d_in[2];
    const float* bq = (const float*)d_in[3];
    const float* wk = (const float*)d_in[4];
    const float* sk = (const float*)d_in[5];
    const float* bk = (const float*)d_in[6];
    const float* wv = (const float*)d_in[7];
    const float* sv = (const float*)d_in[8];
    const float* bv = (const float*)d_in[9];
    const float* wp = (const float*)d_in[10];
    const float* sp = (const float*)d_in[11];
    const float* bp = (const float*)d_in[12];
    float* out = (float*)d_out;

    int prep_total = M1*KD + CC*KD;
    prep_kernel<<<(prep_total + 255)/256, 256>>>(wq,sq,bq, wk,sk,bk, wv,sv,bv, wp,sp,bp);

    // QKV GEMM: 1152 x 25088 flattened
    gemm_kernel<<<dim3(NTILES, M1/64), 128>>>(x, 0);

    // LIF over T + bit packing
    lif1_kernel<<<3*BB*CC, 224>>>();

    // attention + attn-LIF
    attn_kernel<<<BB*HH, 224>>>();

    // projection GEMM: 384 x 25088 flattened
    gemm_kernel<<<dim3(NTILES, CC/64), 128>>>(nullptr, 1);

    // final LIF -> output
    lif2_kernel<<<(BB*CC*NP + 255)/256, 256>>>(out);
}

// round 12
// speedup vs baseline: 1.0004x; 1.0004x over previous
#include <cuda_runtime.h>

#define TT 4
#define BB 32
#define CC 384
#define NP 196
#define HH 8
#define HD 48
#define LB (TT*BB)     // 128 (t,b) batches
#define KD 384
#define M1 1152        // stacked q,k,v output channels
#define NCOLS (LB*NP)  // 25088 flattened columns
#define NTILES (NCOLS/64)  // 392 exactly

typedef unsigned long long u64;

// ---------------- packed f32x2 helpers (Blackwell FFMA2) ----------------
__device__ __forceinline__ u64 pk2(float x) {
    u64 d; asm("mov.b64 %0, {%1, %2};" : "=l"(d) : "f"(x), "f"(x)); return d;
}
__device__ __forceinline__ u64 fma2(u64 a, u64 b, u64 c) {
    u64 d; asm("fma.rn.f32x2 %0, %1, %2, %3;" : "=l"(d) : "l"(a), "l"(b), "l"(c)); return d;
}
__device__ __forceinline__ u64 add2(u64 a, u64 b) {
    u64 d; asm("add.rn.f32x2 %0, %1, %2;" : "=l"(d) : "l"(a), "l"(b)); return d;
}

// ---------------- scratch (static device globals; no allocs) ----------------
__device__ float    g_wqkv[M1*KD];                 // folded scale*W for q,k,v stacked
__device__ float    g_bqkv[M1];
__device__ float    g_wp[CC*KD];                   // folded proj weight
__device__ float    g_bp[CC];
__device__ float    g_y1[(size_t)LB*M1*NP];        // pre-LIF qkv activations
__device__ unsigned g_s1[3*TT*BB*CC*8];            // packed spike bits
__device__ float    g_s2[(size_t)LB*CC*NP];        // attn-LIF spikes as 0/1 floats
__device__ float    g_y3[(size_t)LB*CC*NP];        // pre-LIF proj activations

// ---------------- weight folding ----------------
__global__ void prep_kernel(const float* __restrict__ wq, const float* __restrict__ sq, const float* __restrict__ bq,
                            const float* __restrict__ wk, const float* __restrict__ sk, const float* __restrict__ bk,
                            const float* __restrict__ wv, const float* __restrict__ sv, const float* __restrict__ bv,
                            const float* __restrict__ wp, const float* __restrict__ sp, const float* __restrict__ bp)
{
    int idx = blockIdx.x * blockDim.x + threadIdx.x;
    if (idx < M1*KD) {
        int co = idx / KD, c = idx - co*KD;
        int s  = co / CC,  cp = co - s*CC;
        const float* w  = (s==0) ? wq : (s==1 ? wk : wv);
        const float* sc = (s==0) ? sq : (s==1 ? sk : sv);
        g_wqkv[idx] = w[cp*KD + c] * sc[cp];
        if (c == 0) {
            const float* bi = (s==0) ? bq : (s==1 ? bk : bv);
            g_bqkv[co] = bi[cp];
        }
    } else {
        int j = idx - M1*KD;
        if (j < CC*KD) {
            int cp = j / KD, c = j - cp*KD;
            g_wp[j] = wp[j] * sp[cp];
            if (c == 0) g_bp[cp] = bp[cp];
        }
    }
}

// ---------------- FFMA2 batched GEMM over flattened (l,n) columns ----------------
// C[m, (l,n)] = sum_k A[m,k] * B[l][k,n] + bias[m]
// B memory layout: [l][KD][NP] (x or g_s2).  C layout: [l][M][NP].
// Flattened col cg = l*196 + n; tiles of 64 cols never need bounds checks
// (25088 % 64 == 0) and float4/float2 column groups never cross l (196 % 4 == 0).
// Block: 128 threads, tile 64M x 64N, micro 4M x 8N (4 packed pairs), K-tile 16.
__global__ void __launch_bounds__(128) gemm_kernel(const float* __restrict__ Bext, int stage)
{
    const float* __restrict__ A   = stage ? g_wp  : g_wqkv;
    const float* __restrict__ bia = stage ? g_bp  : g_bqkv;
    const float* __restrict__ Bb  = stage ? g_s2  : Bext;
    float*       __restrict__ Cb  = stage ? g_y3  : g_y1;
    const int M = stage ? CC : M1;

    const int m0 = blockIdx.y * 64;
    const int n0 = blockIdx.x * 64;

    __shared__ float As[16][68];   // [k][m] padded (stride 272B, 16B aligned)
    __shared__ float Bs[16][68];   // [k][n] padded

    const int tid = threadIdx.x;
    const int tx = tid & 7;        // N group (8 cols)
    const int ty = tid >> 3;       // M group (4 rows)

    // ---- A loader: row am, k-quads q0 and q0+2 ----
    const int am = tid >> 1;
    const int q0 = (tid & 1);
    const float* Aptr = A + (size_t)(m0 + am) * KD + q0*4;

    // ---- B loader: k-row bk, col-quads bq and bq+8 ----
    const int bk = tid >> 3;
    const int bq = tid & 7;
    int cg0 = n0 + bq*4;
    int cg1 = n0 + (bq+8)*4;
    int l0 = cg0 / NP, nn0 = cg0 - l0*NP;
    int l1 = cg1 / NP, nn1 = cg1 - l1*NP;
    const float* Bptr0 = Bb + (size_t)l0 * KD * NP + (size_t)bk * NP + nn0;
    const float* Bptr1 = Bb + (size_t)l1 * KD * NP + (size_t)bk * NP + nn1;

    u64 acc[4][4];
#pragma unroll
    for (int i = 0; i < 4; i++)
#pragma unroll
        for (int p = 0; p < 4; p++) acc[i][p] = 0ull;

    // prefetch k0 = 0
    float4 ar0 = *(const float4*)(Aptr);
    float4 ar1 = *(const float4*)(Aptr + 8);
    float4 br0 = *(const float4*)(Bptr0);
    float4 br1 = *(const float4*)(Bptr1);

    for (int k0 = 0; k0 < KD; k0 += 16) {
        // store staged regs to smem (A transposed to [k][m])
        As[q0*4+0][am] = ar0.x;  As[q0*4+1][am] = ar0.y;
        As[q0*4+2][am] = ar0.z;  As[q0*4+3][am] = ar0.w;
        As[q0*4+8][am] = ar1.x;  As[q0*4+9][am] = ar1.y;
        As[q0*4+10][am] = ar1.z; As[q0*4+11][am] = ar1.w;
        *(float4*)&Bs[bk][bq*4]      = br0;
        *(float4*)&Bs[bk][bq*4 + 32] = br1;
        __syncthreads();

        if (k0 + 16 < KD) {
            ar0 = *(const float4*)(Aptr + k0 + 16);
            ar1 = *(const float4*)(Aptr + k0 + 24);
            br0 = *(const float4*)(Bptr0 + (size_t)(k0 + 16) * NP);
            br1 = *(const float4*)(Bptr1 + (size_t)(k0 + 16) * NP);
        }

#pragma unroll
        for (int kk = 0; kk < 16; kk++) {
            float4 af = *(const float4*)&As[kk][ty*4];
            ulonglong2 bp0 = *(const ulonglong2*)&Bs[kk][tx*8];
            ulonglong2 bp1 = *(const ulonglong2*)&Bs[kk][tx*8 + 4];
            u64 a0 = pk2(af.x), a1 = pk2(af.y), a2 = pk2(af.z), a3 = pk2(af.w);
            acc[0][0] = fma2(a0, bp0.x, acc[0][0]);
            acc[0][1] = fma2(a0, bp0.y, acc[0][1]);
            acc[0][2] = fma2(a0, bp1.x, acc[0][2]);
            acc[0][3] = fma2(a0, bp1.y, acc[0][3]);
            acc[1][0] = fma2(a1, bp0.x, acc[1][0]);
            acc[1][1] = fma2(a1, bp0.y, acc[1][1]);
            acc[1][2] = fma2(a1, bp1.x, acc[1][2]);
            acc[1][3] = fma2(a1, bp1.y, acc[1][3]);
            acc[2][0] = fma2(a2, bp0.x, acc[2][0]);
            acc[2][1] = fma2(a2, bp0.y, acc[2][1]);
            acc[2][2] = fma2(a2, bp1.x, acc[2][2]);
            acc[2][3] = fma2(a2, bp1.y, acc[2][3]);
            acc[3][0] = fma2(a3, bp0.x, acc[3][0]);
            acc[3][1] = fma2(a3, bp0.y, acc[3][1]);
            acc[3][2] = fma2(a3, bp1.x, acc[3][2]);
            acc[3][3] = fma2(a3, bp1.y, acc[3][3]);
        }
        __syncthreads();
    }

    // ---- epilogue: bias + store as aligned 8B pairs ----
    size_t coff[4];
#pragma unroll
    for (int p = 0; p < 4; p++) {
        int cg = n0 + tx*8 + 2*p;          // even -> pair stays within one l
        int l = cg / NP;
        int nn = cg - l*NP;
        coff[p] = (size_t)l * M * NP + nn;
    }
#pragma unroll
    for (int i = 0; i < 4; i++) {
        int m = m0 + ty*4 + i;
        u64 bb = pk2(bia[m]);
#pragma unroll
        for (int p = 0; p < 4; p++) {
            u64 r = add2(acc[i][p], bb);
            *(u64*)(Cb + coff[p] + (size_t)m * NP) = r;
        }
    }
}

// ---------------- LIF over T for qkv + pack spikes to bits ----------------
__global__ void __launch_bounds__(224) lif1_kernel()
{
    const int r = blockIdx.x;                 // 0 .. 3*32*384-1
    const int s = r / (BB*CC);
    const int rem = r - s*BB*CC;
    const int b = rem / CC;
    const int c = rem - b*CC;

    const int n = threadIdx.x;
    const int w = n >> 5, lane = n & 31;
    const bool valid = (n < NP);

    const size_t tstride = (size_t)BB * M1 * NP;
    const float* ybase = g_y1 + ((size_t)b*M1 + s*CC + c) * NP + n;

    float v = 0.f;
#pragma unroll
    for (int t = 0; t < TT; t++) {
        float y = valid ? ybase[(size_t)t * tstride] : 0.f;
        v += (y - v) * 0.5f;
        int sp = valid && (v >= 1.f);
        unsigned m = __ballot_sync(0xffffffffu, sp);
        unsigned base = (((unsigned)(s*TT + t) * BB + b) * CC + c) * 8u;
        if (lane == 0) g_s1[base + w] = m;
        if (n == 0)    g_s1[base + 7] = 0u;     // pad word
        if (sp) v = 0.f;
    }
}

// ---------------- attention: out = Q (K^T V) * 0.125, fused attn-LIF(0.5) ----------------
__global__ void __launch_bounds__(224) attn_kernel()
{
    const int bh = blockIdx.x;
    const int b = bh >> 3;
    const int h = bh & 7;

    __shared__ unsigned qb[HD][8], kb[HD][8], vb[HD][8];
    __shared__ float KVf[HD][HD];

    const int tid = threadIdx.x;
    const int n = tid;
    const bool valid = (n < NP);
    const int wq_ = n >> 5, sh = n & 31;

    float vstate[HD];
#pragma unroll
    for (int j = 0; j < HD; j++) vstate[j] = 0.f;

    for (int t = 0; t < TT; t++) {
        for (int i = tid; i < 3*CC; i += 224) {
            int s = i / CC;
            int rr = i - s*CC;
            int dd = rr >> 3, w = rr & 7;
            unsigned val = g_s1[(((unsigned)(s*TT + t) * BB + b) * CC + h*HD + dd) * 8u + w];
            unsigned (*dst)[8] = (s == 0) ? qb : (s == 1 ? kb : vb);
            dst[dd][w] = val;
        }
        __syncthreads();

        for (int p = tid; p < HD*HD; p += 224) {
            int dd = p / HD, d2 = p - dd*HD;
            int cnt = 0;
#pragma unroll
            for (int w = 0; w < 7; w++) cnt += __popc(kb[dd][w] & vb[d2][w]);
            KVf[dd][d2] = (float)cnt;
        }
        __syncthreads();

        if (valid) {
            float acc[HD];
#pragma unroll
            for (int j = 0; j < HD; j++) acc[j] = 0.f;

            for (int dd = 0; dd < HD; dd++) {
                float bf = (float)((qb[dd][wq_] >> sh) & 1u);
#pragma unroll
                for (int j = 0; j < HD; j++) acc[j] += bf * KVf[dd][j];
            }

            float* s2 = g_s2 + (((size_t)t*BB + b) * CC + h*HD) * NP + n;
#pragma unroll
            for (int j = 0; j < HD; j++) {
                float y = acc[j] * 0.125f;
                float v = vstate[j];
                v += (y - v) * 0.5f;
                bool sp = (v >= 0.5f);
                s2[(size_t)j * NP] = sp ? 1.f : 0.f;
                vstate[j] = sp ? 0.f : v;
            }
        }
        __syncthreads();
    }
}

// ---------------- final LIF over T -> output spikes ----------------
__global__ void lif2_kernel(float* __restrict__ out)
{
    const int S = BB*CC*NP;
    int idx = blockIdx.x * blockDim.x + threadIdx.x;
    if (idx >= S) return;
    float v = 0.f;
#pragma unroll
    for (int t = 0; t < TT; t++) {
        float y = g_y3[(size_t)t * S + idx];
        v += (y - v) * 0.5f;
        if (v >= 1.f) { out[(size_t)t * S + idx] = 1.f; v = 0.f; }
        else          { out[(size_t)t * S + idx] = 0.f; }
    }
}

// ---------------- launch ----------------
extern "C" void kernel_launch(void* const* d_in, const int* in_sizes, int n_in,
                              void* d_out, int out_size)
{
    const float* x  = (const float*)d_in[0];
    const float* wq = (const float*)d_in[1];
    const float* sq = (const float*)d_in[2];
    const float* bq = (const float*)d_in[3];
    const float* wk = (const float*)d_in[4];
    const float* sk = (const float*)d_in[5];
    const float* bk = (const float*)d_in[6];
    const float* wv = (const float*)d_in[7];
    const float* sv = (const float*)d_in[8];
    const float* bv = (const float*)d_in[9];
    const float* wp = (const float*)d_in[10];
    const float* sp = (const float*)d_in[11];
    const float* bp = (const float*)d_in[12];
    float* out = (float*)d_out;

    int prep_total = M1*KD + CC*KD;
    prep_kernel<<<(prep_total + 255)/256, 256>>>(wq,sq,bq, wk,sk,bk, wv,sv,bv, wp,sp,bp);

    // QKV GEMM: 1152 x 25088 flattened
    gemm_kernel<<<dim3(NTILES, M1/64), 128>>>(x, 0);

    // LIF over T + bit packing
    lif1_kernel<<<3*BB*CC, 224>>>();

    // attention + attn-LIF
    attn_kernel<<<BB*HH, 224>>>();

    // projection GEMM: 384 x 25088 flattened
    gemm_kernel<<<dim3(NTILES, CC/64), 128>>>(nullptr, 1);

    // final LIF -> output
    lif2_kernel<<<(BB*CC*NP + 255)/256, 256>>>(out);
}

// round 17
// speedup vs baseline: 1.8142x; 1.8135x over previous
#include <cuda_runtime.h>
#include <cuda_bf16.h>
#include <cstdint>

#define TT 4
#define BB 32
#define CC 384
#define NP 196
#define HH 8
#define HD 48
#define LB (TT*BB)       // 128 batches
#define KD 384
#define M1 1152          // stacked q,k,v rows
#define KP 1152          // split-concat K' = 3*384
#define NCOLS (LB*NP)    // 25088
#define NTILE 128
#define NTILES (NCOLS/NTILE) // 196

typedef unsigned long long u64;

// ---------------- scratch (static device globals; no allocs) ----------------
__device__ __align__(16) __nv_bfloat16 g_wqkv_s[(size_t)M1*KP];   // split-concat folded qkv W
__device__ float    g_bqkv[M1];
__device__ __align__(16) __nv_bfloat16 g_wp_s[(size_t)CC*KP];     // split-concat folded proj W
__device__ float    g_bp[CC];
__device__ __align__(16) __nv_bfloat16 g_xs[(size_t)NCOLS*KP];    // x split planes, K-major [col][q*384+k]
__device__ __align__(16) __nv_bfloat16 g_ss[(size_t)NCOLS*KD];    // attn spikes bf16, K-major [col][c]
__device__ __align__(16) float g_y1[(size_t)LB*M1*NP];            // pre-LIF qkv activations
__device__ unsigned g_s1[3*TT*BB*CC*8];                           // packed spike bits
__device__ __align__(16) float g_y3[(size_t)LB*CC*NP];            // pre-LIF proj activations

// ---------------- helpers ----------------
__device__ __forceinline__ uint32_t smem_u32(const void* p) {
    uint32_t a;
    asm("{ .reg .u64 t; cvta.to.shared.u64 t, %1; cvt.u32.u64 %0, t; }" : "=r"(a) : "l"(p));
    return a;
}

// fp32 = h1 + h2 + h3 bf16 split (residuals exact; final residual ~2^-24 rel)
__device__ __forceinline__ void split3(float v, __nv_bfloat16& h1, __nv_bfloat16& h2, __nv_bfloat16& h3) {
    h1 = __float2bfloat16(v);
    float r1 = v - __bfloat162float(h1);
    h2 = __float2bfloat16(r1);
    float r2 = r1 - __bfloat162float(h2);
    h3 = __float2bfloat16(r2);
}

// ---------------- weight folding + bf16 split ----------------
__global__ void prep_kernel(const float* __restrict__ wq, const float* __restrict__ sq, const float* __restrict__ bq,
                            const float* __restrict__ wk, const float* __restrict__ sk, const float* __restrict__ bk,
                            const float* __restrict__ wv, const float* __restrict__ sv, const float* __restrict__ bv,
                            const float* __restrict__ wp, const float* __restrict__ sp, const float* __restrict__ bp)
{
    int idx = blockIdx.x * blockDim.x + threadIdx.x;
    if (idx < M1*KD) {
        int m = idx / KD, k = idx - m*KD;
        int s = m / CC, cp = m - s*CC;
        const float* w  = (s==0) ? wq : (s==1 ? wk : wv);
        const float* sc = (s==0) ? sq : (s==1 ? sk : sv);
        float v = w[cp*KD + k] * sc[cp];
        __nv_bfloat16 h1, h2, h3;
        split3(v, h1, h2, h3);
        size_t base = (size_t)m * KP + k;
        g_wqkv_s[base]       = h1;
        g_wqkv_s[base + 384] = h2;
        g_wqkv_s[base + 768] = h3;
        if (k == 0) {
            const float* bi = (s==0) ? bq : (s==1 ? bk : bv);
            g_bqkv[m] = bi[cp];
        }
    } else {
        int j = idx - M1*KD;
        if (j < CC*KD) {
            int cp = j / KD, k = j - cp*KD;
            float v = wp[j] * sp[cp];
            __nv_bfloat16 h1, h2, h3;
            split3(v, h1, h2, h3);
            size_t base = (size_t)cp * KP + k;
            g_wp_s[base]       = h1;
            g_wp_s[base + 384] = h2;
            g_wp_s[base + 768] = h3;
            if (k == 0) g_bp[cp] = bp[cp];
        }
    }
}

// ---------------- x -> K-major bf16 split planes ----------------
// x: [l][384][196] fp32 -> g_xs[(l*196+n)][q*384 + k] bf16
__global__ void __launch_bounds__(256) splitx_kernel(const float* __restrict__ x)
{
    const int l  = blockIdx.y;     // 0..127
    const int kc = blockIdx.x;     // 0..11, 32 k-rows each
    __shared__ float tile[32][200];

    const float* src = x + (size_t)l*KD*NP + (size_t)kc*32*NP;
    for (int i = threadIdx.x; i < 32*NP; i += 256) {
        int k = i / NP, n = i - k*NP;
        tile[k][n] = src[i];
    }
    __syncthreads();

    for (int i = threadIdx.x; i < NP*8; i += 256) {
        int n = i >> 3, kq = i & 7;                // kq picks 4 consecutive k
        __align__(8) __nv_bfloat16 hp0[4], hp1[4], hp2[4];
#pragma unroll
        for (int j = 0; j < 4; j++) {
            split3(tile[kq*4 + j][n], hp0[j], hp1[j], hp2[j]);
        }
        size_t row = ((size_t)l*NP + n) * KP + kc*32 + kq*4;
        *(u64*)(g_xs + row)        = *(u64*)hp0;
        *(u64*)(g_xs + row + 384)  = *(u64*)hp1;
        *(u64*)(g_xs + row + 768)  = *(u64*)hp2;
    }
}

// ---------------- mma.sync bf16 split GEMM (HMMA path; sm_103 non-'a' safe) ----
// stage 0: g_y1 = Wqkv_fold @ x   (9 split cross-products, 54 K64-chunks)
// stage 1: g_y3 = Wp_fold @ spikes (3 split products, 18 K64-chunks)
// CTA tile 128M x 128N, 256 threads (8 warps, warp tile 64x32), K-chunk 64.
// smem tiles 128 rows x 128B with XOR swizzle: addr = r*128 + (kb ^ ((r&7)*16)).
__global__ void __launch_bounds__(256, 2) gemm_mma(int stage)
{
    const __nv_bfloat16* __restrict__ A  = stage ? g_wp_s : g_wqkv_s;
    const float* __restrict__ bias       = stage ? g_bp   : g_bqkv;
    const __nv_bfloat16* __restrict__ Bp = stage ? g_ss   : g_xs;
    float* __restrict__ C                = stage ? g_y3   : g_y1;
    const int M        = stage ? CC : M1;
    const int bstride  = stage ? KD : KP;
    const int nch      = stage ? 18 : 54;

    extern __shared__ __align__(128) char smem[];
    const uint32_t sb = smem_u32(smem);

    const int tid  = threadIdx.x;
    const int wid  = tid >> 5, lane = tid & 31;
    const int m0   = blockIdx.y * 128;
    const int n0   = blockIdx.x * NTILE;
    const int wm   = (wid >> 2) * 64;     // warp M offset within tile
    const int wn   = (wid & 3) * 32;      // warp N offset within tile

    // ---- ldmatrix lane addressing (precomputed parts) ----
    // A fragment (m16 x k16), x4: groups g=lane>>3: {r,k0},{r+8,k0},{r,k+8},{r+8,k+8}
    const int ar   = wm + (lane & 7) + ((lane >> 3) & 1) * 8;   // row within tile (mt adds 16)
    const int asw  = (ar & 7) * 16;
    const int akx  = (lane >> 4) * 16;                          // +16B for k8-15 groups
    // B fragment (k16 x n8), x2 on col-major smem: lanes 0-7 cols @k0, 8-15 cols @k8
    const int l16  = lane & 15;
    const int br   = wn + (l16 & 7);                            // col within tile (nt adds 8)
    const int bsw  = (br & 7) * 16;
    const int bkx  = ((l16 >> 3) & 1) * 16;

    // ---- loader mapping: 4 passes x 256 threads x 16B = 16KB per tile ----
    const int lr = tid >> 3;          // pass 0 rows 0..31, +32 per pass
    const int lc = (tid & 7) * 16;    // byte col

    float acc[4][4][4];
#pragma unroll
    for (int mt = 0; mt < 4; mt++)
#pragma unroll
        for (int nt = 0; nt < 4; nt++)
#pragma unroll
            for (int r = 0; r < 4; r++) acc[mt][nt][r] = 0.f;

    auto load_chunk = [&](int ci) {
        int p  = ci / 6, kk = ci - p * 6;
        int aoff = (stage ? p : p / 3) * 384 + kk * 64;
        int boff = (stage ? 0 : (p % 3) * 384) + kk * 64;
        uint32_t abuf = sb + (uint32_t)(ci & 1) * 32768u;
        uint32_t bbuf = abuf + 16384u;
#pragma unroll
        for (int ps = 0; ps < 4; ps++) {
            int r = lr + ps * 32;
            uint32_t dsw = (uint32_t)(r * 128 + (lc ^ ((r & 7) * 16)));
            const void* asrc = A  + (size_t)(m0 + r) * KP      + aoff + (lc >> 1);
            const void* bsrc = Bp + (size_t)(n0 + r) * bstride + boff + (lc >> 1);
            asm volatile("cp.async.cg.shared.global [%0], [%1], 16;" :: "r"(abuf + dsw), "l"(asrc) : "memory");
            asm volatile("cp.async.cg.shared.global [%0], [%1], 16;" :: "r"(bbuf + dsw), "l"(bsrc) : "memory");
        }
        asm volatile("cp.async.commit_group;" ::: "memory");
    };

    load_chunk(0);

    for (int ci = 0; ci < nch; ci++) {
        if (ci + 1 < nch) {
            load_chunk(ci + 1);
            asm volatile("cp.async.wait_group 1;" ::: "memory");
        } else {
            asm volatile("cp.async.wait_group 0;" ::: "memory");
        }
        __syncthreads();

        uint32_t abuf = sb + (uint32_t)(ci & 1) * 32768u;
        uint32_t bbuf = abuf + 16384u;

#pragma unroll
        for (int s = 0; s < 4; s++) {
            uint32_t a[4][4], b[4][2];
#pragma unroll
            for (int mt = 0; mt < 4; mt++) {
                uint32_t addr = abuf + (uint32_t)((ar + mt * 16) * 128 + ((s * 32 + akx) ^ asw));
                asm volatile("ldmatrix.sync.aligned.m8n8.x4.shared.b16 {%0,%1,%2,%3}, [%4];"
                             : "=r"(a[mt][0]), "=r"(a[mt][1]), "=r"(a[mt][2]), "=r"(a[mt][3])
                             : "r"(addr));
            }
#pragma unroll
            for (int nt = 0; nt < 4; nt++) {
                uint32_t addr = bbuf + (uint32_t)((br + nt * 8) * 128 + ((s * 32 + bkx) ^ bsw));
                asm volatile("ldmatrix.sync.aligned.m8n8.x2.shared.b16 {%0,%1}, [%2];"
                             : "=r"(b[nt][0]), "=r"(b[nt][1])
                             : "r"(addr));
            }
#pragma unroll
            for (int mt = 0; mt < 4; mt++)
#pragma unroll
                for (int nt = 0; nt < 4; nt++) {
                    asm volatile(
                        "mma.sync.aligned.m16n8k16.row.col.f32.bf16.bf16.f32 "
                        "{%0,%1,%2,%3}, {%4,%5,%6,%7}, {%8,%9}, {%0,%1,%2,%3};"
                        : "+f"(acc[mt][nt][0]), "+f"(acc[mt][nt][1]),
                          "+f"(acc[mt][nt][2]), "+f"(acc[mt][nt][3])
                        : "r"(a[mt][0]), "r"(a[mt][1]), "r"(a[mt][2]), "r"(a[mt][3]),
                          "r"(b[nt][0]), "r"(b[nt][1]));
                }
        }
        __syncthreads();
    }

    // ---- epilogue: bias + store; C layout [l][M][NP], col = l*196 + nn ----
#pragma unroll
    for (int mt = 0; mt < 4; mt++) {
        int r0 = m0 + wm + mt * 16 + (lane >> 2);
        float b0v = bias[r0], b1v = bias[r0 + 8];
#pragma unroll
        for (int nt = 0; nt < 4; nt++) {
            int cg = n0 + wn + nt * 8 + 2 * (lane & 3);   // even -> pair within one l
            int l = cg / NP, nn = cg - l * NP;
            float* base = C + (size_t)l * M * NP + nn;
            float2 v0, v1;
            v0.x = acc[mt][nt][0] + b0v;  v0.y = acc[mt][nt][1] + b0v;
            v1.x = acc[mt][nt][2] + b1v;  v1.y = acc[mt][nt][3] + b1v;
            *(float2*)(base + (size_t)r0 * NP)       = v0;
            *(float2*)(base + (size_t)(r0 + 8) * NP) = v1;
        }
    }
}

// ---------------- LIF over T for qkv + pack spikes to bits ----------------
__global__ void __launch_bounds__(224) lif1_kernel()
{
    const int r = blockIdx.x;                 // 0 .. 3*32*384-1
    const int s = r / (BB*CC);
    const int rem = r - s*BB*CC;
    const int b = rem / CC;
    const int c = rem - b*CC;

    const int n = threadIdx.x;
    const int w = n >> 5, lane = n & 31;
    const bool valid = (n < NP);

    const size_t tstride = (size_t)BB * M1 * NP;
    const float* ybase = g_y1 + ((size_t)b*M1 + s*CC + c) * NP + n;

    float v = 0.f;
#pragma unroll
    for (int t = 0; t < TT; t++) {
        float y = valid ? ybase[(size_t)t * tstride] : 0.f;
        v += (y - v) * 0.5f;
        int sp = valid && (v >= 1.f);
        unsigned m = __ballot_sync(0xffffffffu, sp);
        unsigned base = (((unsigned)(s*TT + t) * BB + b) * CC + c) * 8u;
        if (lane == 0) g_s1[base + w] = m;
        if (n == 0)    g_s1[base + 7] = 0u;     // pad word
        if (sp) v = 0.f;
    }
}

// ---------------- attention: out = Q (K^T V) * 0.125, fused attn-LIF(0.5) ----------------
// writes bf16 spikes K-major into g_ss[(l*196+n)][c]
__global__ void __launch_bounds__(224) attn_kernel()
{
    const int bh = blockIdx.x;
    const int b = bh >> 3;
    const int h = bh & 7;

    __shared__ unsigned qb[HD][8], kb[HD][8], vb[HD][8];
    __shared__ float KVf[HD][HD];

    const int tid = threadIdx.x;
    const int n = tid;
    const bool valid = (n < NP);
    const int wq_ = n >> 5, sh = n & 31;

    float vstate[HD];
#pragma unroll
    for (int j = 0; j < HD; j++) vstate[j] = 0.f;

    const __nv_bfloat16 one  = __float2bfloat16(1.0f);
    const __nv_bfloat16 zero = __float2bfloat16(0.0f);

    for (int t = 0; t < TT; t++) {
        for (int i = tid; i < 3*CC; i += 224) {
            int s = i / CC;
            int rr = i - s*CC;
            int dd = rr >> 3, w = rr & 7;
            unsigned val = g_s1[(((unsigned)(s*TT + t) * BB + b) * CC + h*HD + dd) * 8u + w];
            unsigned (*dst)[8] = (s == 0) ? qb : (s == 1 ? kb : vb);
            dst[dd][w] = val;
        }
        __syncthreads();

        for (int p = tid; p < HD*HD; p += 224) {
            int dd = p / HD, d2 = p - dd*HD;
            int cnt = 0;
#pragma unroll
            for (int w = 0; w < 7; w++) cnt += __popc(kb[dd][w] & vb[d2][w]);
            KVf[dd][d2] = (float)cnt;
        }
        __syncthreads();

        if (valid) {
            float acc[HD];
#pragma unroll
            for (int j = 0; j < HD; j++) acc[j] = 0.f;

            for (int dd = 0; dd < HD; dd++) {
                float bf = (float)((qb[dd][wq_] >> sh) & 1u);
#pragma unroll
                for (int j = 0; j < HD; j++) acc[j] += bf * KVf[dd][j];
            }

            // attn-LIF v_th = 0.5; bf16 spikes K-major for gemm stage 1
            __nv_bfloat16* s2 = g_ss + ((size_t)(t*BB + b) * NP + n) * KD + h*HD;
#pragma unroll
            for (int j = 0; j < HD; j++) {
                float y = acc[j] * 0.125f;
                float v = vstate[j];
                v += (y - v) * 0.5f;
                bool sp = (v >= 0.5f);
                s2[j] = sp ? one : zero;
                vstate[j] = sp ? 0.f : v;
            }
        }
        __syncthreads();
    }
}

// ---------------- final LIF over T -> output spikes ----------------
__global__ void lif2_kernel(float* __restrict__ out)
{
    const int S = BB*CC*NP;
    int idx = blockIdx.x * blockDim.x + threadIdx.x;
    if (idx >= S) return;
    float v = 0.f;
#pragma unroll
    for (int t = 0; t < TT; t++) {
        float y = g_y3[(size_t)t * S + idx];
        v += (y - v) * 0.5f;
        if (v >= 1.f) { out[(size_t)t * S + idx] = 1.f; v = 0.f; }
        else          { out[(size_t)t * S + idx] = 0.f; }
    }
}

// ---------------- launch ----------------
extern "C" void kernel_launch(void* const* d_in, const int* in_sizes, int n_in,
                              void* d_out, int out_size)
{
    const float* x  = (const float*)d_in[0];
    const float* wq = (const float*)d_in[1];
    const float* sq = (const float*)d_in[2];
    const float* bq = (const float*)d_in[3];
    const float* wk = (const float*)d_in[4];
    const float* sk = (const float*)d_in[5];
    const float* bk = (const float*)d_in[6];
    const float* wv = (const float*)d_in[7];
    const float* sv = (const float*)d_in[8];
    const float* bv = (const float*)d_in[9];
    const float* wp = (const float*)d_in[10];
    const float* sp = (const float*)d_in[11];
    const float* bp = (const float*)d_in[12];
    float* out = (float*)d_out;

    const int GEMM_SMEM = 65536;   // double-buffered A(16K)+B(16K)
    cudaFuncSetAttribute(gemm_mma, cudaFuncAttributeMaxDynamicSharedMemorySize, GEMM_SMEM);

    int prep_total = M1*KD + CC*KD;
    prep_kernel<<<(prep_total + 255)/256, 256>>>(wq,sq,bq, wk,sk,bk, wv,sv,bv, wp,sp,bp);

    // x -> bf16 split planes (K-major)
    splitx_kernel<<<dim3(12, LB), 256>>>(x);

    // QKV GEMM (mma.sync, 9 split cross-products): 1152 x 25088
    gemm_mma<<<dim3(NTILES, M1/128), 256, GEMM_SMEM>>>(0);

    // LIF over T + bit packing
    lif1_kernel<<<3*BB*CC, 224>>>();

    // attention + attn-LIF -> bf16 spikes
    attn_kernel<<<BB*HH, 224>>>();

    // projection GEMM (mma.sync, 3 split products): 384 x 25088
    gemm_mma<<<dim3(NTILES, CC/128), 256, GEMM_SMEM>>>(1);

    // final LIF -> output
    lif2_kernel<<<(BB*CC*NP + 255)/256, 256>>>(out);
}